// round 15
// baseline (speedup 1.0000x reference)
#include <cuda_runtime.h>
#include <cuda_bf16.h>
#include <cstdint>
#include <cstring>

#define N_NODES 100000
#define N_EDGES 1600000
#define IN_DIM  512
#define HID_DIM 64
#define NSB ((N_NODES + 1023) / 1024)   // 98 scan blocks

typedef unsigned long long u64;
typedef unsigned int u32;
#define DC_ONE_CNT (((u64)1) << 48)
#define DC_SCALE   1099511627776.0f     // 2^40
#define DC_INV     (1.0f / 1099511627776.0f)
#define DC_MASK    0xFFFFFFFFFFFFULL

// ---------------- scratch (static device globals: allocation-free) ----------
__device__ int   g_idx64;
__device__ u64   g_dc[N_NODES];          // packed: cnt<<48 | fixed-point deg
__device__ u64   g_sstate[NSB];          // lookback state: flag<<32 | value
__device__ float g_dinv[N_NODES];
__device__ int   g_rs[N_NODES + 1];
__device__ int   g_cur[N_NODES];
__device__ int   g_src[N_EDGES];
__device__ float g_w[N_EDGES];
__device__ float g_h[(size_t)N_NODES * HID_DIM];   // GEMM output (both layers)
__device__ float g_h2[(size_t)N_NODES * HID_DIM];  // layer-1 agg output
// bf16 hi/lo split of W, stored [n][k] (B operand)
__device__ __nv_bfloat16 g_b1hi[64 * IN_DIM];
__device__ __nv_bfloat16 g_b1lo[64 * IN_DIM];
__device__ __nv_bfloat16 g_b2hi[64 * HID_DIM];
__device__ __nv_bfloat16 g_b2lo[64 * HID_DIM];

// ---------------- helpers -----------------------------------------------------
__device__ __forceinline__ void mma_bf16(float* c, const uint32_t* a,
                                         uint32_t b0, uint32_t b1) {
    asm("mma.sync.aligned.m16n8k16.row.col.f32.bf16.bf16.f32 "
        "{%0,%1,%2,%3},{%4,%5,%6,%7},{%8,%9},{%0,%1,%2,%3};"
        : "+f"(c[0]), "+f"(c[1]), "+f"(c[2]), "+f"(c[3])
        : "r"(a[0]), "r"(a[1]), "r"(a[2]), "r"(a[3]), "r"(b0), "r"(b1));
}
__device__ __forceinline__ int load_idx(const void* ei, long long pos) {
    if (g_idx64) return (int)((const long long*)ei)[pos];
    return ((const int*)ei)[pos];
}
__device__ __forceinline__ uint32_t bf2u(__nv_bfloat162 t) {
    uint32_t u; memcpy(&u, &t, 4); return u;
}

// ---------------- init: deg/cnt + scan state + dtype detect + W split --------
__global__ void init_kernel(const int* __restrict__ ei32,
                            const float* __restrict__ W1,
                            const float* __restrict__ W2) {
    int i = blockIdx.x * blockDim.x + threadIdx.x;
    // self-loop weight 1.0 in deg; cnt = 0 (self-loop NOT a CSR slot)
    if (i < N_NODES) g_dc[i] = (u64)(1.0f * DC_SCALE);
    if (i < NSB) g_sstate[i] = 0ULL;
    if (blockIdx.x == 0 && threadIdx.x < 32) {
        int nz = 0;
#pragma unroll
        for (int j = 0; j < 4; j++) nz |= ei32[1 + 2 * (threadIdx.x * 4 + j)];
        unsigned b = __ballot_sync(0xffffffffu, nz != 0);
        if (threadIdx.x == 0) g_idx64 = (b == 0u) ? 1 : 0;
    }
    if (i < IN_DIM * 64) {
        int k = i / 64, n = i % 64;
        float w = W1[i];
        __nv_bfloat16 h = __float2bfloat16(w);
        g_b1hi[n * IN_DIM + k] = h;
        g_b1lo[n * IN_DIM + k] = __float2bfloat16(w - __bfloat162float(h));
    }
    if (i < HID_DIM * 64) {
        int k = i / 64, n = i % 64;
        float w = W2[i];
        __nv_bfloat16 h = __float2bfloat16(w);
        g_b2hi[n * HID_DIM + k] = h;
        g_b2lo[n * HID_DIM + k] = __float2bfloat16(w - __bfloat162float(h));
    }
}

// one packed 64-bit atomic per edge
__global__ void deg_hist_kernel(const void* __restrict__ ei,
                                const float* __restrict__ ew) {
    int e = blockIdx.x * blockDim.x + threadIdx.x;
    if (e >= N_EDGES) return;
    int d = load_idx(ei, (long long)N_EDGES + e);
    if ((unsigned)d < (unsigned)N_NODES) {
        u64 p = DC_ONE_CNT + (u64)(ew[e] * DC_SCALE);
        atomicAdd(&g_dc[d], p);
    }
}

// ---------------- single-pass decoupled-lookback scan + dinv -----------------
__global__ void __launch_bounds__(1024) scan_kernel() {
    __shared__ int ws[32];
    __shared__ int s_excl;
    int b = blockIdx.x, tid = threadIdx.x, lane = tid & 31, wid = tid >> 5;
    int i = b * 1024 + tid;

    u64 p = (i < N_NODES) ? g_dc[i] : 0ULL;
    if (i < N_NODES) {
        float deg = (float)(p & DC_MASK) * DC_INV;
        g_dinv[i] = (deg > 0.0f) ? rsqrtf(deg) : 0.0f;
    }
    int v = (int)(p >> 48);
    int x = v;
#pragma unroll
    for (int off = 1; off < 32; off <<= 1) {
        int y = __shfl_up_sync(0xffffffffu, x, off);
        if (lane >= off) x += y;
    }
    if (lane == 31) ws[wid] = x;
    __syncthreads();
    if (wid == 0) {
        int s = ws[lane];
#pragma unroll
        for (int off = 1; off < 32; off <<= 1) {
            int y = __shfl_up_sync(0xffffffffu, s, off);
            if (lane >= off) s += y;
        }
        ws[lane] = s;
    }
    __syncthreads();
    int incl = x + (wid > 0 ? ws[wid - 1] : 0);

    if (tid == 1023 && b > 0)
        atomicExch(&g_sstate[b], (1ULL << 32) | (u32)incl);

    if (tid == 0) {
        int excl = 0;
        int pb = b - 1;
        while (pb >= 0) {
            u64 st = atomicAdd(&g_sstate[pb], 0ULL);
            u32 f = (u32)(st >> 32);
            if (f == 0u) continue;
            excl += (int)(u32)st;
            if (f == 2u) break;
            pb--;
        }
        s_excl = excl;
    }
    __syncthreads();
    int excl = s_excl;

    if (tid == 1023)
        atomicExch(&g_sstate[b], (2ULL << 32) | (u32)(excl + incl));

    if (i < N_NODES) {
        int r = excl + incl - v;
        g_rs[i] = r;
        g_cur[i] = r;
    }
    if (b == NSB - 1 && tid == 1023) g_rs[N_NODES] = excl + incl;
}

__global__ void reorder_kernel(const void* __restrict__ ei,
                               const float* __restrict__ ew) {
    int e = blockIdx.x * blockDim.x + threadIdx.x;
    if (e >= N_EDGES) return;
    int s = load_idx(ei, e);
    int d = load_idx(ei, (long long)N_EDGES + e);
    if ((unsigned)d >= (unsigned)N_NODES) return;
    int p = atomicAdd(&g_cur[d], 1);
    if ((unsigned)s < (unsigned)N_NODES) {
        g_src[p] = s;
        g_w[p]   = g_dinv[s] * ew[e] * g_dinv[d];
    } else {
        g_src[p] = 0;
        g_w[p]   = 0.0f;
    }
}

// ---------------- GEMM: g_h[M,64] = X[M,K] @ W[K,64], bf16 3-pass -----------
// 128 threads (4 warps). Warp tile 32 rows (2 m16 tiles) x 64 cols -> B
// fragments reused 2x (halves B smem reads). K chunked by 16, smem stride 12
// (conflict-free fragment LDS). Register prefetch of next chunk overlaps MMA.
// Truncation hi/lo split: hi = bits&0xFFFF0000 (exact), lo = x - hi.
template <int K, bool FROM_G_H2>
__global__ void __launch_bounds__(128) mma_gemm_kernel(
    const float* __restrict__ Xext) {
    __shared__ uint32_t ash[128][12];
    __shared__ uint32_t asl[128][12];
    __shared__ uint32_t bsh[64][12];
    __shared__ uint32_t bsl[64][12];

    const float* X = FROM_G_H2 ? (const float*)g_h2 : Xext;
    const __nv_bfloat16* Bhi = (K == IN_DIM) ? g_b1hi : g_b2hi;
    const __nv_bfloat16* Blo = (K == IN_DIM) ? g_b1lo : g_b2lo;

    const int M = N_NODES;
    constexpr int CH = K / 16;
    int t = threadIdx.x, wid = t >> 5, lane = t & 31;
    int g = lane >> 2, tig = lane & 3;
    int rowBase = blockIdx.x * 128;

    // A slots: 128 rows x 4 quads = 512 float4 / 128 thr = 4 each
    int arow[4], aq[4];
#pragma unroll
    for (int it = 0; it < 4; it++) {
        int id = t + it * 128;
        arow[it] = id >> 2;
        aq[it]   = id & 3;
    }
    // B slots: 64 rows x 2 quads, hi and lo -> thread t owns hi[t] and lo[t]
    int brow = t >> 1, bu = t & 1;

    float4 av[4];
    uint4 bvh, bvl;

    // prologue: load chunk 0
#pragma unroll
    for (int it = 0; it < 4; it++) {
        int gr = rowBase + arow[it];
        av[it] = (gr < M) ? *(const float4*)(X + (size_t)gr * K + aq[it] * 4)
                          : make_float4(0.f, 0.f, 0.f, 0.f);
    }
    bvh = *(const uint4*)(Bhi + (size_t)brow * K + bu * 8);
    bvl = *(const uint4*)(Blo + (size_t)brow * K + bu * 8);

    float acc[2][8][4] = {};

    for (int ch = 0; ch < CH; ch++) {
        // convert + store current regs to smem
#pragma unroll
        for (int it = 0; it < 4; it++) {
            float4 v = av[it];
            uint32_t xb = __float_as_uint(v.x), yb = __float_as_uint(v.y);
            uint32_t zb = __float_as_uint(v.z), wb = __float_as_uint(v.w);
            uint32_t h0 = __byte_perm(xb, yb, 0x7632);
            uint32_t h1 = __byte_perm(zb, wb, 0x7632);
            float lx = v.x - __uint_as_float(xb & 0xFFFF0000u);
            float ly = v.y - __uint_as_float(yb & 0xFFFF0000u);
            float lz = v.z - __uint_as_float(zb & 0xFFFF0000u);
            float lw = v.w - __uint_as_float(wb & 0xFFFF0000u);
            uint32_t l0 = bf2u(__floats2bfloat162_rn(lx, ly));
            uint32_t l1 = bf2u(__floats2bfloat162_rn(lz, lw));
            ash[arow[it]][aq[it] * 2]     = h0;
            ash[arow[it]][aq[it] * 2 + 1] = h1;
            asl[arow[it]][aq[it] * 2]     = l0;
            asl[arow[it]][aq[it] * 2 + 1] = l1;
        }
        *(uint4*)&bsh[brow][bu * 4] = bvh;
        *(uint4*)&bsl[brow][bu * 4] = bvl;
        __syncthreads();

        // prefetch next chunk (LDGs fly during the MMA phase)
        if (ch + 1 < CH) {
            int k0n = (ch + 1) * 16;
#pragma unroll
            for (int it = 0; it < 4; it++) {
                int gr = rowBase + arow[it];
                av[it] = (gr < M)
                    ? *(const float4*)(X + (size_t)gr * K + k0n + aq[it] * 4)
                    : make_float4(0.f, 0.f, 0.f, 0.f);
            }
            bvh = *(const uint4*)(Bhi + (size_t)brow * K + k0n + bu * 8);
            bvl = *(const uint4*)(Blo + (size_t)brow * K + k0n + bu * 8);
        }

        // MMA phase: one k16 step, fragments w0=tig, w1=tig+4
        {
            int w0 = tig, w1 = tig + 4;
            uint32_t ah[2][4], al[2][4];
#pragma unroll
            for (int mt = 0; mt < 2; mt++) {
                int r = wid * 32 + mt * 16 + g;
                ah[mt][0] = ash[r][w0];  ah[mt][1] = ash[r + 8][w0];
                ah[mt][2] = ash[r][w1];  ah[mt][3] = ash[r + 8][w1];
                al[mt][0] = asl[r][w0];  al[mt][1] = asl[r + 8][w0];
                al[mt][2] = asl[r][w1];  al[mt][3] = asl[r + 8][w1];
            }
#pragma unroll
            for (int nt = 0; nt < 8; nt++) {
                int n = nt * 8 + g;
                uint32_t bh0 = bsh[n][w0], bh1 = bsh[n][w1];
                uint32_t bl0 = bsl[n][w0], bl1 = bsl[n][w1];
#pragma unroll
                for (int mt = 0; mt < 2; mt++) {
                    mma_bf16(acc[mt][nt], ah[mt], bh0, bh1);
                    mma_bf16(acc[mt][nt], ah[mt], bl0, bl1);
                    mma_bf16(acc[mt][nt], al[mt], bh0, bh1);
                }
            }
        }
        __syncthreads();
    }

    // epilogue
#pragma unroll
    for (int mt = 0; mt < 2; mt++) {
        int r0g = rowBase + wid * 32 + mt * 16 + g;
#pragma unroll
        for (int nt = 0; nt < 8; nt++) {
            int col = nt * 8 + tig * 2;
            if (r0g < M)
                *(float2*)(g_h + (size_t)r0g * 64 + col) =
                    make_float2(acc[mt][nt][0], acc[mt][nt][1]);
            if (r0g + 8 < M)
                *(float2*)(g_h + (size_t)(r0g + 8) * 64 + col) =
                    make_float2(acc[mt][nt][2], acc[mt][nt][3]);
        }
    }
}

// ---------------- aggregation: warp per node, CSR gather, no atomics --------
template <bool RELU>
__global__ void __launch_bounds__(256) agg_kernel(
    const float* __restrict__ bias, float2* __restrict__ outp) {
    const float2* H = (const float2*)g_h;
    float2* out = RELU ? (float2*)g_h2 : outp;

    int gw   = (blockIdx.x * blockDim.x + threadIdx.x) >> 5;
    int lane = threadIdx.x & 31;
    if (gw >= N_NODES) return;
    int node = gw;

    float di = g_dinv[node];
    float sn = di * di;
    float2 hv = H[(size_t)node * 32 + lane];
    float ax = sn * hv.x, ay = sn * hv.y;

    int b = g_rs[node], en = g_rs[node + 1];
    for (int i = b; i < en; i += 32) {
        int rem = en - i;
        int src = 0; float w = 0.f;
        if (lane < rem) { src = g_src[i + lane]; w = g_w[i + lane]; }
        int m = rem < 32 ? rem : 32;
        int j = 0;
        for (; j + 4 <= m; j += 4) {
            int   s0 = __shfl_sync(0xffffffffu, src, j);
            int   s1 = __shfl_sync(0xffffffffu, src, j + 1);
            int   s2 = __shfl_sync(0xffffffffu, src, j + 2);
            int   s3 = __shfl_sync(0xffffffffu, src, j + 3);
            float w0 = __shfl_sync(0xffffffffu, w, j);
            float w1 = __shfl_sync(0xffffffffu, w, j + 1);
            float w2 = __shfl_sync(0xffffffffu, w, j + 2);
            float w3 = __shfl_sync(0xffffffffu, w, j + 3);
            float2 x0 = H[(size_t)s0 * 32 + lane];
            float2 x1 = H[(size_t)s1 * 32 + lane];
            float2 x2 = H[(size_t)s2 * 32 + lane];
            float2 x3 = H[(size_t)s3 * 32 + lane];
            ax += w0 * x0.x; ay += w0 * x0.y;
            ax += w1 * x1.x; ay += w1 * x1.y;
            ax += w2 * x2.x; ay += w2 * x2.y;
            ax += w3 * x3.x; ay += w3 * x3.y;
        }
        for (; j < m; j++) {
            int   s0 = __shfl_sync(0xffffffffu, src, j);
            float w0 = __shfl_sync(0xffffffffu, w, j);
            float2 x0 = H[(size_t)s0 * 32 + lane];
            ax += w0 * x0.x; ay += w0 * x0.y;
        }
    }
    float2 bb = ((const float2*)bias)[lane];
    ax += bb.x; ay += bb.y;
    if (RELU) { ax = fmaxf(ax, 0.f); ay = fmaxf(ay, 0.f); }
    out[(size_t)node * 32 + lane] = make_float2(ax, ay);
}

// ---------------- launch -----------------------------------------------------
extern "C" void kernel_launch(void* const* d_in, const int* in_sizes, int n_in,
                              void* d_out, int out_size) {
    const float* x   = (const float*)d_in[0];
    const void*  ei  = d_in[1];
    const float* ew  = (const float*)d_in[2];
    const float* W1  = (const float*)d_in[3];
    const float* b1  = (const float*)d_in[4];
    const float* W2  = (const float*)d_in[5];
    const float* b2  = (const float*)d_in[6];
    float*       out = (float*)d_out;

    const int TPB = 256;
    int nBlocksN = (N_NODES + TPB - 1) / TPB;
    int nBlocksE = (N_EDGES + TPB - 1) / TPB;
    int gemmBlocks = (N_NODES + 127) / 128;
    int aggBlocks  = (N_NODES + 7) / 8;

    init_kernel<<<nBlocksN, TPB>>>((const int*)ei, W1, W2);
    deg_hist_kernel<<<nBlocksE, TPB>>>(ei, ew);
    scan_kernel<<<NSB, 1024>>>();
    mma_gemm_kernel<IN_DIM, false><<<gemmBlocks, 128>>>(x);   // launch #4: profiled
    reorder_kernel<<<nBlocksE, TPB>>>(ei, ew);

    agg_kernel<true><<<aggBlocks, TPB>>>(b1, nullptr);
    mma_gemm_kernel<HID_DIM, true><<<gemmBlocks, 128>>>(nullptr);
    agg_kernel<false><<<aggBlocks, TPB>>>(b2, (float2*)out);
}

// round 16
// speedup vs baseline: 1.0005x; 1.0005x over previous
#include <cuda_runtime.h>
#include <cuda_bf16.h>
#include <cstdint>
#include <cstring>

#define N_NODES 100000
#define N_EDGES 1600000
#define IN_DIM  512
#define HID_DIM 64
#define NSB ((N_NODES + 1023) / 1024)   // 98 scan blocks

typedef unsigned long long u64;
typedef unsigned int u32;
#define DC_ONE_CNT (((u64)1) << 48)
#define DC_SCALE   1099511627776.0f     // 2^40
#define DC_INV     (1.0f / 1099511627776.0f)
#define DC_MASK    0xFFFFFFFFFFFFULL

// ---------------- scratch (static device globals: allocation-free) ----------
__device__ int   g_idx64;
__device__ u64   g_dc[N_NODES];          // packed: cnt<<48 | fixed-point deg
__device__ u64   g_sstate[NSB];          // lookback state: flag<<32 | value
__device__ float g_dinv[N_NODES];
__device__ int   g_rs[N_NODES + 1];
__device__ int   g_cur[N_NODES];
__device__ int   g_src[N_EDGES];
__device__ float g_w[N_EDGES];
__device__ float g_h[(size_t)N_NODES * HID_DIM];   // GEMM output (both layers)
__device__ float g_h2[(size_t)N_NODES * HID_DIM];  // layer-1 agg output
// bf16 hi/lo split of W, stored [n][k] (B operand)
__device__ __nv_bfloat16 g_b1hi[64 * IN_DIM];
__device__ __nv_bfloat16 g_b1lo[64 * IN_DIM];
__device__ __nv_bfloat16 g_b2hi[64 * HID_DIM];
__device__ __nv_bfloat16 g_b2lo[64 * HID_DIM];

// ---------------- helpers -----------------------------------------------------
__device__ __forceinline__ void mma_bf16(float* c, const uint32_t* a,
                                         uint32_t b0, uint32_t b1) {
    asm("mma.sync.aligned.m16n8k16.row.col.f32.bf16.bf16.f32 "
        "{%0,%1,%2,%3},{%4,%5,%6,%7},{%8,%9},{%0,%1,%2,%3};"
        : "+f"(c[0]), "+f"(c[1]), "+f"(c[2]), "+f"(c[3])
        : "r"(a[0]), "r"(a[1]), "r"(a[2]), "r"(a[3]), "r"(b0), "r"(b1));
}
__device__ __forceinline__ int load_idx(const void* ei, long long pos) {
    if (g_idx64) return (int)((const long long*)ei)[pos];
    return ((const int*)ei)[pos];
}
__device__ __forceinline__ uint32_t bf2u(__nv_bfloat162 t) {
    uint32_t u; memcpy(&u, &t, 4); return u;
}
// fp32 pair -> hi word (truncation, exact) + lo word (residual, rn)
__device__ __forceinline__ void split2(float x, float y, uint32_t& hi, uint32_t& lo) {
    uint32_t xb = __float_as_uint(x), yb = __float_as_uint(y);
    hi = __byte_perm(xb, yb, 0x7632);
    float lx = x - __uint_as_float(xb & 0xFFFF0000u);
    float ly = y - __uint_as_float(yb & 0xFFFF0000u);
    lo = bf2u(__floats2bfloat162_rn(lx, ly));
}

// ---------------- init: deg/cnt + scan state + dtype detect + W split --------
__global__ void init_kernel(const int* __restrict__ ei32,
                            const float* __restrict__ W1,
                            const float* __restrict__ W2) {
    int i = blockIdx.x * blockDim.x + threadIdx.x;
    if (i < N_NODES) g_dc[i] = (u64)(1.0f * DC_SCALE);   // self-loop weight only
    if (i < NSB) g_sstate[i] = 0ULL;
    if (blockIdx.x == 0 && threadIdx.x < 32) {
        int nz = 0;
#pragma unroll
        for (int j = 0; j < 4; j++) nz |= ei32[1 + 2 * (threadIdx.x * 4 + j)];
        unsigned b = __ballot_sync(0xffffffffu, nz != 0);
        if (threadIdx.x == 0) g_idx64 = (b == 0u) ? 1 : 0;
    }
    if (i < IN_DIM * 64) {
        int k = i / 64, n = i % 64;
        float w = W1[i];
        __nv_bfloat16 h = __float2bfloat16(w);
        g_b1hi[n * IN_DIM + k] = h;
        g_b1lo[n * IN_DIM + k] = __float2bfloat16(w - __bfloat162float(h));
    }
    if (i < HID_DIM * 64) {
        int k = i / 64, n = i % 64;
        float w = W2[i];
        __nv_bfloat16 h = __float2bfloat16(w);
        g_b2hi[n * HID_DIM + k] = h;
        g_b2lo[n * HID_DIM + k] = __float2bfloat16(w - __bfloat162float(h));
    }
}

// one packed 64-bit atomic per edge
__global__ void deg_hist_kernel(const void* __restrict__ ei,
                                const float* __restrict__ ew) {
    int e = blockIdx.x * blockDim.x + threadIdx.x;
    if (e >= N_EDGES) return;
    int d = load_idx(ei, (long long)N_EDGES + e);
    if ((unsigned)d < (unsigned)N_NODES) {
        u64 p = DC_ONE_CNT + (u64)(ew[e] * DC_SCALE);
        atomicAdd(&g_dc[d], p);
    }
}

// ---------------- single-pass decoupled-lookback scan + dinv -----------------
__global__ void __launch_bounds__(1024) scan_kernel() {
    __shared__ int ws[32];
    __shared__ int s_excl;
    int b = blockIdx.x, tid = threadIdx.x, lane = tid & 31, wid = tid >> 5;
    int i = b * 1024 + tid;

    u64 p = (i < N_NODES) ? g_dc[i] : 0ULL;
    if (i < N_NODES) {
        float deg = (float)(p & DC_MASK) * DC_INV;
        g_dinv[i] = (deg > 0.0f) ? rsqrtf(deg) : 0.0f;
    }
    int v = (int)(p >> 48);
    int x = v;
#pragma unroll
    for (int off = 1; off < 32; off <<= 1) {
        int y = __shfl_up_sync(0xffffffffu, x, off);
        if (lane >= off) x += y;
    }
    if (lane == 31) ws[wid] = x;
    __syncthreads();
    if (wid == 0) {
        int s = ws[lane];
#pragma unroll
        for (int off = 1; off < 32; off <<= 1) {
            int y = __shfl_up_sync(0xffffffffu, s, off);
            if (lane >= off) s += y;
        }
        ws[lane] = s;
    }
    __syncthreads();
    int incl = x + (wid > 0 ? ws[wid - 1] : 0);

    if (tid == 1023 && b > 0)
        atomicExch(&g_sstate[b], (1ULL << 32) | (u32)incl);

    if (tid == 0) {
        int excl = 0;
        int pb = b - 1;
        while (pb >= 0) {
            u64 st = atomicAdd(&g_sstate[pb], 0ULL);
            u32 f = (u32)(st >> 32);
            if (f == 0u) continue;
            excl += (int)(u32)st;
            if (f == 2u) break;
            pb--;
        }
        s_excl = excl;
    }
    __syncthreads();
    int excl = s_excl;

    if (tid == 1023)
        atomicExch(&g_sstate[b], (2ULL << 32) | (u32)(excl + incl));

    if (i < N_NODES) {
        int r = excl + incl - v;
        g_rs[i] = r;
        g_cur[i] = r;
    }
    if (b == NSB - 1 && tid == 1023) g_rs[N_NODES] = excl + incl;
}

__global__ void reorder_kernel(const void* __restrict__ ei,
                               const float* __restrict__ ew) {
    int e = blockIdx.x * blockDim.x + threadIdx.x;
    if (e >= N_EDGES) return;
    int s = load_idx(ei, e);
    int d = load_idx(ei, (long long)N_EDGES + e);
    if ((unsigned)d >= (unsigned)N_NODES) return;
    int p = atomicAdd(&g_cur[d], 1);
    if ((unsigned)s < (unsigned)N_NODES) {
        g_src[p] = s;
        g_w[p]   = g_dinv[s] * ew[e] * g_dinv[d];
    } else {
        g_src[p] = 0;
        g_w[p]   = 0.0f;
    }
}

// ---------------- GEMM: g_h[M,64] = X[M,K] @ W[K,64], bf16 3-pass -----------
// 256 threads (8 warps), CTA tile 256 rows x 64. Warp tile 32 rows.
// A: direct LDG.64 in fragment layout -> register convert (NO smem for A).
// B: smem, double-buffered (stride 12 = conflict-free), 1 sync per chunk.
// K chunked by 16. Truncation hi/lo split.
template <int K, bool FROM_G_H2>
__global__ void __launch_bounds__(256) mma_gemm_kernel(
    const float* __restrict__ Xext) {
    __shared__ uint32_t bsh[2][64][12];
    __shared__ uint32_t bsl[2][64][12];

    const float* X = FROM_G_H2 ? (const float*)g_h2 : Xext;
    const __nv_bfloat16* Bhi = (K == IN_DIM) ? g_b1hi : g_b2hi;
    const __nv_bfloat16* Blo = (K == IN_DIM) ? g_b1lo : g_b2lo;

    const int M = N_NODES;
    constexpr int CH = K / 16;
    int t = threadIdx.x, wid = t >> 5, lane = t & 31;
    int g = lane >> 2, tig = lane & 3;
    int rowBase = blockIdx.x * 256;

    // A fragment rows/cols for this thread
    int r0 = rowBase + wid * 32 + g;          // mt=0 rows r0, r0+8
    int r1 = r0 + 16;                          // mt=1 rows r1, r1+8
    // B load slot: thread t owns row t>>2, 4-element group t&3 (uint2 hi+lo)
    int brow = t >> 2, bwu = t & 3;

    float2 av[8];        // [mt*4 + seg*2 + ro]: seg 0 = k 2tig.., seg 1 = k 8+2tig..
    uint2 bvh, bvl;

    // prologue: load chunk 0
    {
        const int rows[4] = {r0, r0 + 8, r1, r1 + 8};
#pragma unroll
        for (int mt = 0; mt < 2; mt++)
#pragma unroll
            for (int ro = 0; ro < 2; ro++) {
                int gr = rows[mt * 2 + ro];
                bool ok = gr < M;
                av[mt * 4 + 0 * 2 + ro] = ok ? *(const float2*)(X + (size_t)gr * K + 2 * tig)
                                             : make_float2(0.f, 0.f);
                av[mt * 4 + 1 * 2 + ro] = ok ? *(const float2*)(X + (size_t)gr * K + 8 + 2 * tig)
                                             : make_float2(0.f, 0.f);
            }
        bvh = *(const uint2*)(Bhi + (size_t)brow * K + bwu * 4);
        bvl = *(const uint2*)(Blo + (size_t)brow * K + bwu * 4);
    }

    float acc[2][8][4] = {};

    for (int ch = 0; ch < CH; ch++) {
        int p = ch & 1;
        // store current B regs to smem buffer p
        bsh[p][brow][bwu * 2]     = bvh.x;
        bsh[p][brow][bwu * 2 + 1] = bvh.y;
        bsl[p][brow][bwu * 2]     = bvl.x;
        bsl[p][brow][bwu * 2 + 1] = bvl.y;

        // convert current A regs to fragments (A never touches smem)
        uint32_t ah[2][4], al[2][4];
#pragma unroll
        for (int mt = 0; mt < 2; mt++)
#pragma unroll
            for (int fi = 0; fi < 4; fi++) {
                // fragment fi: 0=(r,w0) 1=(r+8,w0) 2=(r,w1) 3=(r+8,w1)
                int seg = fi >> 1, ro = fi & 1;
                float2 v = av[mt * 4 + seg * 2 + ro];
                split2(v.x, v.y, ah[mt][fi], al[mt][fi]);
            }
        __syncthreads();

        // prefetch next chunk into regs (LDGs overlap the MMA phase)
        if (ch + 1 < CH) {
            int k0n = (ch + 1) * 16;
            const int rows[4] = {r0, r0 + 8, r1, r1 + 8};
#pragma unroll
            for (int mt = 0; mt < 2; mt++)
#pragma unroll
                for (int ro = 0; ro < 2; ro++) {
                    int gr = rows[mt * 2 + ro];
                    bool ok = gr < M;
                    av[mt * 4 + 0 * 2 + ro] = ok ? *(const float2*)(X + (size_t)gr * K + k0n + 2 * tig)
                                                 : make_float2(0.f, 0.f);
                    av[mt * 4 + 1 * 2 + ro] = ok ? *(const float2*)(X + (size_t)gr * K + k0n + 8 + 2 * tig)
                                                 : make_float2(0.f, 0.f);
                }
            bvh = *(const uint2*)(Bhi + (size_t)brow * K + k0n + bwu * 4);
            bvl = *(const uint2*)(Blo + (size_t)brow * K + k0n + bwu * 4);
        }

        // MMA phase: fragments w0=tig, w1=tig+4 on buffer p
        int w0 = tig, w1 = tig + 4;
#pragma unroll
        for (int nt = 0; nt < 8; nt++) {
            int n = nt * 8 + g;
            uint32_t bh0 = bsh[p][n][w0], bh1 = bsh[p][n][w1];
            uint32_t bl0 = bsl[p][n][w0], bl1 = bsl[p][n][w1];
#pragma unroll
            for (int mt = 0; mt < 2; mt++) {
                mma_bf16(acc[mt][nt], ah[mt], bh0, bh1);
                mma_bf16(acc[mt][nt], ah[mt], bl0, bl1);
                mma_bf16(acc[mt][nt], al[mt], bh0, bh1);
            }
        }
    }

    // epilogue
#pragma unroll
    for (int mt = 0; mt < 2; mt++) {
        int r0g = rowBase + wid * 32 + mt * 16 + g;
#pragma unroll
        for (int nt = 0; nt < 8; nt++) {
            int col = nt * 8 + tig * 2;
            if (r0g < M)
                *(float2*)(g_h + (size_t)r0g * 64 + col) =
                    make_float2(acc[mt][nt][0], acc[mt][nt][1]);
            if (r0g + 8 < M)
                *(float2*)(g_h + (size_t)(r0g + 8) * 64 + col) =
                    make_float2(acc[mt][nt][2], acc[mt][nt][3]);
        }
    }
}

// ---------------- aggregation: warp per node, CSR gather, no atomics --------
template <bool RELU>
__global__ void __launch_bounds__(256) agg_kernel(
    const float* __restrict__ bias, float2* __restrict__ outp) {
    const float2* H = (const float2*)g_h;
    float2* out = RELU ? (float2*)g_h2 : outp;

    int gw   = (blockIdx.x * blockDim.x + threadIdx.x) >> 5;
    int lane = threadIdx.x & 31;
    if (gw >= N_NODES) return;
    int node = gw;

    float di = g_dinv[node];
    float sn = di * di;
    float2 hv = H[(size_t)node * 32 + lane];
    float ax = sn * hv.x, ay = sn * hv.y;

    int b = g_rs[node], en = g_rs[node + 1];
    for (int i = b; i < en; i += 32) {
        int rem = en - i;
        int src = 0; float w = 0.f;
        if (lane < rem) { src = g_src[i + lane]; w = g_w[i + lane]; }
        int m = rem < 32 ? rem : 32;
        int j = 0;
        for (; j + 4 <= m; j += 4) {
            int   s0 = __shfl_sync(0xffffffffu, src, j);
            int   s1 = __shfl_sync(0xffffffffu, src, j + 1);
            int   s2 = __shfl_sync(0xffffffffu, src, j + 2);
            int   s3 = __shfl_sync(0xffffffffu, src, j + 3);
            float w0 = __shfl_sync(0xffffffffu, w, j);
            float w1 = __shfl_sync(0xffffffffu, w, j + 1);
            float w2 = __shfl_sync(0xffffffffu, w, j + 2);
            float w3 = __shfl_sync(0xffffffffu, w, j + 3);
            float2 x0 = H[(size_t)s0 * 32 + lane];
            float2 x1 = H[(size_t)s1 * 32 + lane];
            float2 x2 = H[(size_t)s2 * 32 + lane];
            float2 x3 = H[(size_t)s3 * 32 + lane];
            ax += w0 * x0.x; ay += w0 * x0.y;
            ax += w1 * x1.x; ay += w1 * x1.y;
            ax += w2 * x2.x; ay += w2 * x2.y;
            ax += w3 * x3.x; ay += w3 * x3.y;
        }
        for (; j < m; j++) {
            int   s0 = __shfl_sync(0xffffffffu, src, j);
            float w0 = __shfl_sync(0xffffffffu, w, j);
            float2 x0 = H[(size_t)s0 * 32 + lane];
            ax += w0 * x0.x; ay += w0 * x0.y;
        }
    }
    float2 bb = ((const float2*)bias)[lane];
    ax += bb.x; ay += bb.y;
    if (RELU) { ax = fmaxf(ax, 0.f); ay = fmaxf(ay, 0.f); }
    out[(size_t)node * 32 + lane] = make_float2(ax, ay);
}

// ---------------- launch -----------------------------------------------------
extern "C" void kernel_launch(void* const* d_in, const int* in_sizes, int n_in,
                              void* d_out, int out_size) {
    const float* x   = (const float*)d_in[0];
    const void*  ei  = d_in[1];
    const float* ew  = (const float*)d_in[2];
    const float* W1  = (const float*)d_in[3];
    const float* b1  = (const float*)d_in[4];
    const float* W2  = (const float*)d_in[5];
    const float* b2  = (const float*)d_in[6];
    float*       out = (float*)d_out;

    const int TPB = 256;
    int nBlocksN = (N_NODES + TPB - 1) / TPB;
    int nBlocksE = (N_EDGES + TPB - 1) / TPB;
    int gemmBlocks = (N_NODES + 255) / 256;   // 391
    int aggBlocks  = (N_NODES + 7) / 8;

    init_kernel<<<nBlocksN, TPB>>>((const int*)ei, W1, W2);
    deg_hist_kernel<<<nBlocksE, TPB>>>(ei, ew);
    scan_kernel<<<NSB, 1024>>>();
    mma_gemm_kernel<IN_DIM, false><<<gemmBlocks, 256>>>(x);   // launch #4: profiled
    reorder_kernel<<<nBlocksE, TPB>>>(ei, ew);

    agg_kernel<true><<<aggBlocks, TPB>>>(b1, nullptr);
    mma_gemm_kernel<HID_DIM, true><<<gemmBlocks, 256>>>(nullptr);
    agg_kernel<false><<<aggBlocks, TPB>>>(b2, (float2*)out);
}